// round 14
// baseline (speedup 1.0000x reference)
#include <cuda_runtime.h>
#include <math.h>

// ---------------------------------------------------------------------------
// Problem constants
//   x:  (2, 64, 192, 192)
//   out:(2, 64, 384, 384) fp32
// ---------------------------------------------------------------------------
#define B_   2
#define C_   64
#define H1_  192
#define W1_  192
#define H2_  384
#define W2_  384

// ---------------------------------------------------------------------------
// f32x2 packed-FMA helpers (sm_103a FFMA2 — only reachable via PTX)
// ---------------------------------------------------------------------------
__device__ __forceinline__ unsigned long long pack2(float v) {
    unsigned long long r;
    asm("mov.b64 %0, {%1, %1};" : "=l"(r) : "f"(v));
    return r;
}
__device__ __forceinline__ void fma2(unsigned long long& d,
                                     unsigned long long a,
                                     unsigned long long b) {
    asm("fma.rn.f32x2 %0, %1, %2, %0;" : "+l"(d) : "l"(a), "l"(b));
}
__device__ __forceinline__ float2 unpack2(unsigned long long v) {
    float2 f;
    asm("mov.b64 {%0, %1}, %2;" : "=f"(f.x), "=f"(f.y) : "l"(v));
    return f;
}

// ---------------------------------------------------------------------------
// Scratch (static device globals; no cudaMalloc allowed)
// ---------------------------------------------------------------------------
__device__ float g_off1[B_ * 27 * H1_ * W1_];   // offsets stage 1
__device__ float g_h1  [B_ * C_ * H1_ * W1_];   // elu(dcn1)
__device__ float g_h1up[B_ * C_ * H2_ * W2_];   // upsample2x(h1)
__device__ float g_off2[B_ * 27 * H2_ * W2_];   // offsets stage 2
__device__ float g_r   [B_ * C_ * H1_ * W1_];   // 1x1 residual conv (192^2)
__device__ float g_rup [B_ * C_ * H2_ * W2_];   // upsample2x(r)  (384^2)
__device__ float g_w1t [9 * 64 * 64];           // dcn1 weights (k,c,o)
__device__ float g_w2t [9 * 64 * 64];           // dcn2 weights (k,c,o)
__device__ float g_ow1t[64 * 9 * 32];           // offset conv1 weights (c,k,o-pad32)
__device__ float g_ow2t[64 * 9 * 32];           // offset conv2 weights (c,k,o-pad32)

// ---------------------------------------------------------------------------
// Merged weight transposes (one launch)
// ---------------------------------------------------------------------------
__global__ void transpose_all_kernel(const float* __restrict__ w1,
                                     const float* __restrict__ w2,
                                     const float* __restrict__ ow1,
                                     const float* __restrict__ ow2) {
    int i = blockIdx.x * 256 + threadIdx.x;
    if (i < 2 * 36864) {
        const float* w = (i < 36864) ? w1 : w2;
        float* wt = (i < 36864) ? g_w1t : g_w2t;
        int j = (i < 36864) ? i : i - 36864;
        int o = j & 63;
        int c = (j >> 6) & 63;
        int k = j >> 12;
        wt[j] = w[(o * 64 + c) * 9 + k];
    } else {
        int j = i - 2 * 36864;
        if (j >= 2 * 18432) return;
        const float* w = (j < 18432) ? ow1 : ow2;
        float* wt = (j < 18432) ? g_ow1t : g_ow2t;
        int jj = (j < 18432) ? j : j - 18432;
        int c = jj / 288;
        int r = jj - c * 288;
        int k = r >> 5;
        int o = r & 31;
        wt[jj] = (o < 27) ? w[(o * 64 + c) * 9 + k] : 0.0f;
    }
}

// ---------------------------------------------------------------------------
// 3x3 conv, Cin=64, Cout=27 (28 acc = 14 f32x2 per row group), pad=1, NCHW
// Templated tile height TR: block = 256 thr = 16 x TR tile, TR/16 rows/thread.
// Double-buffered halo+weights, one sync per channel.
// ---------------------------------------------------------------------------
template <int TR>
__global__ void __launch_bounds__(256) conv3x3_27_kernel(
    const float* __restrict__ in,    // (B,64,H,W)
    const float* __restrict__ wt,    // (64,9,32) transposed+padded
    const float* __restrict__ bias,  // (27)
    float* __restrict__ out,         // (B,27,H,W)
    int H, int W)
{
    constexpr int NR = TR + 2;
    constexpr int CNT = NR * 18;
    constexpr int SLOTS = (CNT + 255) / 256;
    constexpr int RG = TR / 16;

    __shared__ __align__(16) float tile[2][NR][18];
    __shared__ __align__(16) float wsm[2][288];

    const int tid = threadIdx.x;
    const int tx = tid & 15;
    const int ty = tid >> 4;
    const int bx = blockIdx.x * 16;
    const int by = blockIdx.y * TR;
    const int b  = blockIdx.z;

    int gofs[SLOTS];
    bool gval[SLOTS];
    bool ghave[SLOTS];
#pragma unroll
    for (int s = 0; s < SLOTS; s++) {
        int idx = tid + s * 256;
        ghave[s] = (idx < CNT);
        int iy = idx / 18, ix = idx - iy * 18;
        int yy = by + iy - 1, xx = bx + ix - 1;
        gval[s] = ghave[s] && (yy >= 0 && yy < H && xx >= 0 && xx < W);
        gofs[s] = yy * W + xx;
    }
    const bool haveW1 = (tid < 32);

    unsigned long long acc2[RG][14];
#pragma unroll
    for (int rg = 0; rg < RG; rg++)
#pragma unroll
        for (int j = 0; j < 14; j++) acc2[rg][j] = 0ULL;

    const float* pc = in + (size_t)b * 64 * H * W;
    const float* pw = wt;
    const int HW = H * W;

#pragma unroll
    for (int s = 0; s < SLOTS; s++)
        if (ghave[s])
            ((float*)tile[0])[tid + s * 256] = gval[s] ? __ldg(pc + gofs[s]) : 0.0f;
    wsm[0][tid] = __ldg(pw + tid);
    if (haveW1) wsm[0][tid + 256] = __ldg(pw + tid + 256);
    __syncthreads();

    for (int c = 0; c < 64; c++) {
        const int cur = c & 1;

        float nv[SLOTS];
        float nw0 = 0.0f, nw1 = 0.0f;
        if (c < 63) {
            const float* pn = pc + HW;
            const float* pwn = pw + 288;
#pragma unroll
            for (int s = 0; s < SLOTS; s++)
                nv[s] = (ghave[s] && gval[s]) ? __ldg(pn + gofs[s]) : 0.0f;
            nw0 = __ldg(pwn + tid);
            if (haveW1) nw1 = __ldg(pwn + tid + 256);
        }

#pragma unroll
        for (int k = 0; k < 9; k++) {
            const ulonglong2* wr = (const ulonglong2*)(&wsm[cur][k * 32]);
#pragma unroll
            for (int rg = 0; rg < RG; rg++) {
                float xv = tile[cur][ty + rg * 16 + k / 3][tx + k % 3];
                unsigned long long xv2 = pack2(xv);
#pragma unroll
                for (int g = 0; g < 7; g++) {
                    ulonglong2 wv = wr[g];
                    fma2(acc2[rg][2 * g + 0], xv2, wv.x);
                    fma2(acc2[rg][2 * g + 1], xv2, wv.y);
                }
            }
        }

        if (c < 63) {
            const int nxt = cur ^ 1;
#pragma unroll
            for (int s = 0; s < SLOTS; s++)
                if (ghave[s]) ((float*)tile[nxt])[tid + s * 256] = nv[s];
            wsm[nxt][tid] = nw0;
            if (haveW1) wsm[nxt][tid + 256] = nw1;
        }
        __syncthreads();
        pc += HW;
        pw += 288;
    }

    const int gx = bx + tx;
#pragma unroll
    for (int rg = 0; rg < RG; rg++) {
        const int gy = by + ty + rg * 16;
        float fa[28];
#pragma unroll
        for (int j = 0; j < 14; j++) {
            float2 t0 = unpack2(acc2[rg][j]);
            fa[2 * j] = t0.x; fa[2 * j + 1] = t0.y;
        }
#pragma unroll
        for (int o = 0; o < 27; o++)
            out[(((size_t)b * 27 + o) * H + gy) * W + gx] = fa[o] + __ldg(bias + o);
    }
}

// ---------------------------------------------------------------------------
// 1x1 conv, 64->64 (residual path), f32x2
// ---------------------------------------------------------------------------
__global__ void __launch_bounds__(256) conv1x1_kernel(
    const float* __restrict__ in,   // (B,64,HW)
    const float* __restrict__ w,    // (64,64) (o,c)
    const float* __restrict__ bias, // (64)
    float* __restrict__ out,        // (B,64,HW)
    int HW)
{
    __shared__ __align__(16) float ws[64 * 64];  // transposed: ws[c*64+o]
    const int tid = threadIdx.x;
    for (int i = tid; i < 4096; i += 256) {
        int c = i >> 6, o = i & 63;
        ws[i] = __ldg(w + o * 64 + c);
    }
    __syncthreads();

    const int b = blockIdx.y;
    const int p = blockIdx.x * 256 + tid;
    if (p >= HW) return;

    const float* inb = in + (size_t)b * 64 * HW + p;
    unsigned long long acc2[32];
#pragma unroll
    for (int j = 0; j < 32; j++) acc2[j] = 0ULL;

    for (int c = 0; c < 64; c++) {
        float xv = __ldg(inb + (size_t)c * HW);
        unsigned long long vv = pack2(xv);
        const ulonglong2* wr = (const ulonglong2*)(ws + c * 64);
#pragma unroll
        for (int g = 0; g < 16; g++) {
            ulonglong2 t = wr[g];
            fma2(acc2[2 * g + 0], vv, t.x);
            fma2(acc2[2 * g + 1], vv, t.y);
        }
    }
    float* ob = out + (size_t)b * 64 * HW + p;
#pragma unroll
    for (int j = 0; j < 32; j++) {
        float2 f = unpack2(acc2[j]);
        ob[(size_t)(2 * j + 0) * HW] = f.x + __ldg(bias + 2 * j + 0);
        ob[(size_t)(2 * j + 1) * HW] = f.y + __ldg(bias + 2 * j + 1);
    }
}

// ---------------------------------------------------------------------------
// bilinear 2x upsample, jax.image.resize semantics
// ---------------------------------------------------------------------------
__global__ void __launch_bounds__(256) upsample2x_kernel(
    const float* __restrict__ in, float* __restrict__ out, int BC, int H, int W)
{
    const int W2 = 2 * W, H2 = 2 * H;
    int idx = blockIdx.x * 256 + threadIdx.x;
    int total = BC * H2 * W2;
    if (idx >= total) return;
    int x = idx % W2;
    int t = idx / W2;
    int y = t % H2;
    int c = t / H2;
    float sy = y * 0.5f - 0.25f;
    float sx = x * 0.5f - 0.25f;
    float y0f = floorf(sy), x0f = floorf(sx);
    float wy = sy - y0f, wx = sx - x0f;
    int y0 = (int)y0f, x0 = (int)x0f;
    int yc0 = min(max(y0, 0), H - 1), yc1 = min(max(y0 + 1, 0), H - 1);
    int xc0 = min(max(x0, 0), W - 1), xc1 = min(max(x0 + 1, 0), W - 1);
    const float* p = in + (size_t)c * H * W;
    float v = (1.0f - wy) * ((1.0f - wx) * __ldg(p + yc0 * W + xc0) + wx * __ldg(p + yc0 * W + xc1))
            +         wy  * ((1.0f - wx) * __ldg(p + yc1 * W + xc0) + wx * __ldg(p + yc1 * W + xc1));
    out[idx] = v;
}

// ---------------------------------------------------------------------------
// DCNv2 + ELU (+ optional residual add for stage 2; residual is PRE-UPSAMPLED
// so the epilogue load is a single coalesced LDG per output).
// Block = 128 threads = 4 warps. Tile = 128 pixels (TILEW cols x ROWS rows).
// Phase 1: warp w gathers channels [16w,16w+16) for its 4 px/thread -> s_s.
// Phase 2: warp w owns outputs [16w,16w+16) x 128 px; weights via LDS128.
// PREF: offset prefetch across taps (measured: on for RES variant only).
// ---------------------------------------------------------------------------
template <int H, int W, int TILEW, int ROWS, bool RES, bool PREF>
__global__ void __launch_bounds__(128) dcn_kernel(
    const float* __restrict__ img,   // (B,64,H,W)
    const float* __restrict__ off,   // (B,27,H,W)
    const float* __restrict__ wt,    // (9,64,64) (k,c,o)
    const float* __restrict__ bias,  // (64)
    const float* __restrict__ res,   // (B,64,H,W) pre-upsampled, or nullptr
    float* __restrict__ out)         // (B,64,H,W)
{
    static_assert(TILEW * ROWS == 128, "tile must be 128 px");
    __shared__ __align__(16) float s_s[64][128];  // [c][px]
    __shared__ __align__(16) float w_s[4096];     // one tap's 64x64 slab

    const int tid  = threadIdx.x;
    const int lane = tid & 31;
    const int warp = tid >> 5;          // 0..3
    const int cgrp = warp * 16;         // phase-1 channel group == phase-2 o group
    const int h0 = blockIdx.y * ROWS;
    const int bx = blockIdx.x * TILEW;
    const int b  = blockIdx.z;
    const int HW = H * W;
    const float* imgb = img + (size_t)b * 64 * HW;
    const float* offb = off + (size_t)b * 27 * HW;

    // this thread's 4 pixels: px = lane + q*32
    int pwv[4], hv[4], pidx[4];
#pragma unroll
    for (int q = 0; q < 4; q++) {
        int px  = lane + q * 32;
        int row = px / TILEW;
        int col = px - row * TILEW;
        pwv[q] = bx + col;
        hv[q]  = h0 + row;
        pidx[q] = hv[q] * W + pwv[q];
    }

    unsigned long long acc[32];   // [o-pair j(8)][px q(4)] -> acc[j*4+q]
#pragma unroll
    for (int i = 0; i < 32; i++) acc[i] = 0ULL;

    float pdy[4], pdx[4], pmz[4];
    if (PREF) {
#pragma unroll
        for (int q = 0; q < 4; q++) {
            pdy[q] = __ldg(offb + 0 * HW + pidx[q]);
            pdx[q] = __ldg(offb + 1 * HW + pidx[q]);
            pmz[q] = __ldg(offb + 18 * HW + pidx[q]);
        }
    }

    for (int k = 0; k < 9; k++) {
        __syncthreads();  // protect s_s / w_s against previous iteration's readers
        // stage this tap's 64x64 weight slab (128 threads x 8 float4)
        {
            const float4* src = (const float4*)(wt + k * 4096);
            float4* dst = (float4*)w_s;
#pragma unroll
            for (int i = tid; i < 1024; i += 128) dst[i] = src[i];
        }

        // tap params for 4 pixels
        float w00[4], w01[4], w10[4], w11[4];
        int i00[4], i01[4], i10[4], i11[4];
#pragma unroll
        for (int q = 0; q < 4; q++) {
            float dy, dx, mz;
            if (PREF) {
                dy = pdy[q]; dx = pdx[q]; mz = pmz[q];
            } else {
                dy = __ldg(offb + (2 * k) * HW + pidx[q]);
                dx = __ldg(offb + (2 * k + 1) * HW + pidx[q]);
                mz = __ldg(offb + (18 + k) * HW + pidx[q]);
            }
            float m  = 1.0f / (1.0f + expf(-mz));

            float yy = (float)(hv[q] - 1 + k / 3) + dy;
            float xx = (float)(pwv[q] - 1 + k % 3) + dx;
            float y0f = floorf(yy), x0f = floorf(xx);
            float wy = yy - y0f, wx = xx - x0f;
            int y0 = (int)y0f, x0 = (int)x0f;
            int y1 = y0 + 1,   x1 = x0 + 1;
            float fy0 = (y0 >= 0 && y0 < H) ? 1.0f : 0.0f;
            float fy1 = (y1 >= 0 && y1 < H) ? 1.0f : 0.0f;
            float fx0 = (x0 >= 0 && x0 < W) ? 1.0f : 0.0f;
            float fx1 = (x1 >= 0 && x1 < W) ? 1.0f : 0.0f;
            w00[q] = (1.0f - wy) * (1.0f - wx) * fy0 * fx0 * m;
            w01[q] = (1.0f - wy) * wx          * fy0 * fx1 * m;
            w10[q] = wy          * (1.0f - wx) * fy1 * fx0 * m;
            w11[q] = wy          * wx          * fy1 * fx1 * m;
            int yc0 = min(max(y0, 0), H - 1), yc1 = min(max(y1, 0), H - 1);
            int xc0 = min(max(x0, 0), W - 1), xc1 = min(max(x1, 0), W - 1);
            i00[q] = yc0 * W + xc0; i01[q] = yc0 * W + xc1;
            i10[q] = yc1 * W + xc0; i11[q] = yc1 * W + xc1;
        }

        // phase 1: this warp's 16 channels x this thread's 4 pixels
        const float* pc = imgb + (size_t)cgrp * HW;
#pragma unroll
        for (int cc = 0; cc < 16; cc++) {
#pragma unroll
            for (int q = 0; q < 4; q++) {
                float s = w00[q] * __ldg(pc + i00[q]) + w01[q] * __ldg(pc + i01[q])
                        + w10[q] * __ldg(pc + i10[q]) + w11[q] * __ldg(pc + i11[q]);
                s_s[cgrp + cc][lane + q * 32] = s;
            }
            pc += HW;
        }
        __syncthreads();

        // prefetch NEXT tap's offsets (latency hides under GEMM below)
        if (PREF && k < 8) {
#pragma unroll
            for (int q = 0; q < 4; q++) {
                pdy[q] = __ldg(offb + (2 * k + 2) * HW + pidx[q]);
                pdx[q] = __ldg(offb + (2 * k + 3) * HW + pidx[q]);
                pmz[q] = __ldg(offb + (19 + k) * HW + pidx[q]);
            }
        }

        // phase 2: warp's 16 outputs x 128 pixels, 32 FFMA2 per c per thread
#pragma unroll 4
        for (int c = 0; c < 64; c++) {
            unsigned long long v[4];
#pragma unroll
            for (int q = 0; q < 4; q++) v[q] = pack2(s_s[c][lane + q * 32]);
            const ulonglong2* wr = (const ulonglong2*)(w_s + c * 64 + cgrp);
            ulonglong2 wp0 = wr[0], wp1 = wr[1], wp2 = wr[2], wp3 = wr[3];
#pragma unroll
            for (int q = 0; q < 4; q++) {
                fma2(acc[0 * 4 + q], v[q], wp0.x);
                fma2(acc[1 * 4 + q], v[q], wp0.y);
                fma2(acc[2 * 4 + q], v[q], wp1.x);
                fma2(acc[3 * 4 + q], v[q], wp1.y);
                fma2(acc[4 * 4 + q], v[q], wp2.x);
                fma2(acc[5 * 4 + q], v[q], wp2.y);
                fma2(acc[6 * 4 + q], v[q], wp3.x);
                fma2(acc[7 * 4 + q], v[q], wp3.y);
            }
        }
    }

    // epilogue: bias, ELU, optional coalesced residual add
    const float* resb = RES ? (res + (size_t)b * 64 * HW) : nullptr;

#pragma unroll
    for (int j = 0; j < 8; j++) {
        int o0 = cgrp + 2 * j;
        float b0 = __ldg(bias + o0);
        float b1 = __ldg(bias + o0 + 1);
#pragma unroll
        for (int q = 0; q < 4; q++) {
            float2 f = unpack2(acc[j * 4 + q]);
            float v0 = f.x + b0;
            float v1 = f.y + b1;
            v0 = v0 > 0.0f ? v0 : expm1f(v0);
            v1 = v1 > 0.0f ? v1 : expm1f(v1);
            const size_t base0 = (((size_t)b * 64 + o0) * H + hv[q]) * W + pwv[q];
            const size_t base1 = base0 + (size_t)HW;
            if (RES) {
                v0 += __ldg(resb + ((size_t)o0 * H + hv[q]) * W + pwv[q]);
                v1 += __ldg(resb + ((size_t)(o0 + 1) * H + hv[q]) * W + pwv[q]);
            }
            out[base0] = v0;
            out[base1] = v1;
        }
    }
}

// ---------------------------------------------------------------------------
// kernel_launch
// inputs: x, ow1, ob1, w1, b1, ow2, ob2, w2, b2, rw, rb
// ---------------------------------------------------------------------------
extern "C" void kernel_launch(void* const* d_in, const int* in_sizes, int n_in,
                              void* d_out, int out_size) {
    (void)in_sizes; (void)n_in; (void)out_size;
    const float* x   = (const float*)d_in[0];
    const float* ow1 = (const float*)d_in[1];
    const float* ob1 = (const float*)d_in[2];
    const float* w1  = (const float*)d_in[3];
    const float* b1  = (const float*)d_in[4];
    const float* ow2 = (const float*)d_in[5];
    const float* ob2 = (const float*)d_in[6];
    const float* w2  = (const float*)d_in[7];
    const float* b2  = (const float*)d_in[8];
    const float* rw  = (const float*)d_in[9];
    const float* rb  = (const float*)d_in[10];
    float* out = (float*)d_out;

    float *off1, *h1, *h1up, *off2, *r, *rup, *w1t, *w2t, *ow1t, *ow2t;
    cudaGetSymbolAddress((void**)&off1, g_off1);
    cudaGetSymbolAddress((void**)&h1,   g_h1);
    cudaGetSymbolAddress((void**)&h1up, g_h1up);
    cudaGetSymbolAddress((void**)&off2, g_off2);
    cudaGetSymbolAddress((void**)&r,    g_r);
    cudaGetSymbolAddress((void**)&rup,  g_rup);
    cudaGetSymbolAddress((void**)&w1t,  g_w1t);
    cudaGetSymbolAddress((void**)&w2t,  g_w2t);
    cudaGetSymbolAddress((void**)&ow1t, g_ow1t);
    cudaGetSymbolAddress((void**)&ow2t, g_ow2t);

    // 0: all weight transposes in one launch
    transpose_all_kernel<<<(110592 + 255) / 256, 256>>>(w1, w2, ow1, ow2);

    // 1: residual path 1x1 conv at 192^2
    conv1x1_kernel<<<dim3((H1_ * W1_ + 255) / 256, B_), 256>>>(x, rw, rb, r, H1_ * W1_);

    // 2: stage-1 offsets — 16x16 tiles (grid 288; R12 measured win)
    conv3x3_27_kernel<16><<<dim3(W1_ / 16, H1_ / 16, B_), 256>>>(x, ow1t, ob1, off1, H1_, W1_);

    // 3: stage-1 dcn + elu (64x2 tile = 128 px), NO prefetch (measured best)
    dcn_kernel<H1_, W1_, 64, 2, false, false><<<dim3(W1_ / 64, H1_ / 2, B_), 128>>>(x, off1, w1t, b1, nullptr, h1);

    // 4: residual upsample r -> rup (replaces 256 scattered epilogue LDGs/thread
    //    in dcn2 with 64 coalesced ones)
    upsample2x_kernel<<<(B_ * C_ * H2_ * W2_ + 255) / 256, 256>>>(r, rup, B_ * C_, H1_, W1_);

    // 5: upsample h1 -> h1up
    upsample2x_kernel<<<(B_ * C_ * H2_ * W2_ + 255) / 256, 256>>>(h1, h1up, B_ * C_, H1_, W1_);

    // 6: stage-2 offsets — 16x16 tiles (grid 1152; occupancy up vs TR=32)
    conv3x3_27_kernel<16><<<dim3(W2_ / 16, H2_ / 16, B_), 256>>>(h1up, ow2t, ob2, off2, H2_, W2_);

    // 7: stage-2 dcn + elu + coalesced residual add, WITH prefetch (measured best)
    dcn_kernel<H2_, W2_, 128, 1, true, true><<<dim3(W2_ / 128, H2_, B_), 128>>>(h1up, off2, w2t, b2, rup, out);
}

// round 15
// speedup vs baseline: 1.0221x; 1.0221x over previous
#include <cuda_runtime.h>
#include <math.h>

// ---------------------------------------------------------------------------
// Problem constants
//   x:  (2, 64, 192, 192)
//   out:(2, 64, 384, 384) fp32
// ---------------------------------------------------------------------------
#define B_   2
#define C_   64
#define H1_  192
#define W1_  192
#define H2_  384
#define W2_  384

// ---------------------------------------------------------------------------
// f32x2 packed-FMA helpers (sm_103a FFMA2 — only reachable via PTX)
// ---------------------------------------------------------------------------
__device__ __forceinline__ unsigned long long pack2(float v) {
    unsigned long long r;
    asm("mov.b64 %0, {%1, %1};" : "=l"(r) : "f"(v));
    return r;
}
__device__ __forceinline__ void fma2(unsigned long long& d,
                                     unsigned long long a,
                                     unsigned long long b) {
    asm("fma.rn.f32x2 %0, %1, %2, %0;" : "+l"(d) : "l"(a), "l"(b));
}
__device__ __forceinline__ float2 unpack2(unsigned long long v) {
    float2 f;
    asm("mov.b64 {%0, %1}, %2;" : "=f"(f.x), "=f"(f.y) : "l"(v));
    return f;
}

// ---------------------------------------------------------------------------
// Scratch (static device globals; no cudaMalloc allowed)
// ---------------------------------------------------------------------------
__device__ float g_off1[B_ * 27 * H1_ * W1_];   // offsets stage 1
__device__ float g_h1  [B_ * C_ * H1_ * W1_];   // elu(dcn1)
__device__ float g_h1up[B_ * C_ * H2_ * W2_];   // upsample2x(h1)
__device__ float g_off2[B_ * 27 * H2_ * W2_];   // offsets stage 2
__device__ float g_r   [B_ * C_ * H1_ * W1_];   // 1x1 residual conv
__device__ float g_w1t [9 * 64 * 64];           // dcn1 weights (k,c,o)
__device__ float g_w2t [9 * 64 * 64];           // dcn2 weights (k,c,o)
__device__ float g_ow1t[64 * 9 * 32];           // offset conv1 weights (c,k,o-pad32)
__device__ float g_ow2t[64 * 9 * 32];           // offset conv2 weights (c,k,o-pad32)

// ---------------------------------------------------------------------------
// Merged weight transposes (one launch)
// ---------------------------------------------------------------------------
__global__ void transpose_all_kernel(const float* __restrict__ w1,
                                     const float* __restrict__ w2,
                                     const float* __restrict__ ow1,
                                     const float* __restrict__ ow2) {
    int i = blockIdx.x * 256 + threadIdx.x;
    if (i < 2 * 36864) {
        const float* w = (i < 36864) ? w1 : w2;
        float* wt = (i < 36864) ? g_w1t : g_w2t;
        int j = (i < 36864) ? i : i - 36864;
        int o = j & 63;
        int c = (j >> 6) & 63;
        int k = j >> 12;
        wt[j] = w[(o * 64 + c) * 9 + k];
    } else {
        int j = i - 2 * 36864;
        if (j >= 2 * 18432) return;
        const float* w = (j < 18432) ? ow1 : ow2;
        float* wt = (j < 18432) ? g_ow1t : g_ow2t;
        int jj = (j < 18432) ? j : j - 18432;
        int c = jj / 288;
        int r = jj - c * 288;
        int k = r >> 5;
        int o = r & 31;
        wt[jj] = (o < 27) ? w[(o * 64 + c) * 9 + k] : 0.0f;
    }
}

// ---------------------------------------------------------------------------
// 3x3 conv, Cin=64, Cout=27 (28 acc = 14 f32x2 per row group), pad=1, NCHW
// Templated tile height TR: block = 256 thr = 16 x TR tile, TR/16 rows/thread.
// Double-buffered halo+weights, one sync per channel.  (R12 configuration)
// ---------------------------------------------------------------------------
template <int TR>
__global__ void __launch_bounds__(256) conv3x3_27_kernel(
    const float* __restrict__ in,    // (B,64,H,W)
    const float* __restrict__ wt,    // (64,9,32) transposed+padded
    const float* __restrict__ bias,  // (27)
    float* __restrict__ out,         // (B,27,H,W)
    int H, int W)
{
    constexpr int NR = TR + 2;
    constexpr int CNT = NR * 18;
    constexpr int SLOTS = (CNT + 255) / 256;
    constexpr int RG = TR / 16;

    __shared__ __align__(16) float tile[2][NR][18];
    __shared__ __align__(16) float wsm[2][288];

    const int tid = threadIdx.x;
    const int tx = tid & 15;
    const int ty = tid >> 4;
    const int bx = blockIdx.x * 16;
    const int by = blockIdx.y * TR;
    const int b  = blockIdx.z;

    int gofs[SLOTS];
    bool gval[SLOTS];
    bool ghave[SLOTS];
#pragma unroll
    for (int s = 0; s < SLOTS; s++) {
        int idx = tid + s * 256;
        ghave[s] = (idx < CNT);
        int iy = idx / 18, ix = idx - iy * 18;
        int yy = by + iy - 1, xx = bx + ix - 1;
        gval[s] = ghave[s] && (yy >= 0 && yy < H && xx >= 0 && xx < W);
        gofs[s] = yy * W + xx;
    }
    const bool haveW1 = (tid < 32);

    unsigned long long acc2[RG][14];
#pragma unroll
    for (int rg = 0; rg < RG; rg++)
#pragma unroll
        for (int j = 0; j < 14; j++) acc2[rg][j] = 0ULL;

    const float* pc = in + (size_t)b * 64 * H * W;
    const float* pw = wt;
    const int HW = H * W;

#pragma unroll
    for (int s = 0; s < SLOTS; s++)
        if (ghave[s])
            ((float*)tile[0])[tid + s * 256] = gval[s] ? __ldg(pc + gofs[s]) : 0.0f;
    wsm[0][tid] = __ldg(pw + tid);
    if (haveW1) wsm[0][tid + 256] = __ldg(pw + tid + 256);
    __syncthreads();

    for (int c = 0; c < 64; c++) {
        const int cur = c & 1;

        float nv[SLOTS];
        float nw0 = 0.0f, nw1 = 0.0f;
        if (c < 63) {
            const float* pn = pc + HW;
            const float* pwn = pw + 288;
#pragma unroll
            for (int s = 0; s < SLOTS; s++)
                nv[s] = (ghave[s] && gval[s]) ? __ldg(pn + gofs[s]) : 0.0f;
            nw0 = __ldg(pwn + tid);
            if (haveW1) nw1 = __ldg(pwn + tid + 256);
        }

#pragma unroll
        for (int k = 0; k < 9; k++) {
            const ulonglong2* wr = (const ulonglong2*)(&wsm[cur][k * 32]);
#pragma unroll
            for (int rg = 0; rg < RG; rg++) {
                float xv = tile[cur][ty + rg * 16 + k / 3][tx + k % 3];
                unsigned long long xv2 = pack2(xv);
#pragma unroll
                for (int g = 0; g < 7; g++) {
                    ulonglong2 wv = wr[g];
                    fma2(acc2[rg][2 * g + 0], xv2, wv.x);
                    fma2(acc2[rg][2 * g + 1], xv2, wv.y);
                }
            }
        }

        if (c < 63) {
            const int nxt = cur ^ 1;
#pragma unroll
            for (int s = 0; s < SLOTS; s++)
                if (ghave[s]) ((float*)tile[nxt])[tid + s * 256] = nv[s];
            wsm[nxt][tid] = nw0;
            if (haveW1) wsm[nxt][tid + 256] = nw1;
        }
        __syncthreads();
        pc += HW;
        pw += 288;
    }

    const int gx = bx + tx;
#pragma unroll
    for (int rg = 0; rg < RG; rg++) {
        const int gy = by + ty + rg * 16;
        float fa[28];
#pragma unroll
        for (int j = 0; j < 14; j++) {
            float2 t0 = unpack2(acc2[rg][j]);
            fa[2 * j] = t0.x; fa[2 * j + 1] = t0.y;
        }
#pragma unroll
        for (int o = 0; o < 27; o++)
            out[(((size_t)b * 27 + o) * H + gy) * W + gx] = fa[o] + __ldg(bias + o);
    }
}

// ---------------------------------------------------------------------------
// 1x1 conv, 64->64 (residual path), f32x2
// ---------------------------------------------------------------------------
__global__ void __launch_bounds__(256) conv1x1_kernel(
    const float* __restrict__ in,   // (B,64,HW)
    const float* __restrict__ w,    // (64,64) (o,c)
    const float* __restrict__ bias, // (64)
    float* __restrict__ out,        // (B,64,HW)
    int HW)
{
    __shared__ __align__(16) float ws[64 * 64];  // transposed: ws[c*64+o]
    const int tid = threadIdx.x;
    for (int i = tid; i < 4096; i += 256) {
        int c = i >> 6, o = i & 63;
        ws[i] = __ldg(w + o * 64 + c);
    }
    __syncthreads();

    const int b = blockIdx.y;
    const int p = blockIdx.x * 256 + tid;
    if (p >= HW) return;

    const float* inb = in + (size_t)b * 64 * HW + p;
    unsigned long long acc2[32];
#pragma unroll
    for (int j = 0; j < 32; j++) acc2[j] = 0ULL;

    for (int c = 0; c < 64; c++) {
        float xv = __ldg(inb + (size_t)c * HW);
        unsigned long long vv = pack2(xv);
        const ulonglong2* wr = (const ulonglong2*)(ws + c * 64);
#pragma unroll
        for (int g = 0; g < 16; g++) {
            ulonglong2 t = wr[g];
            fma2(acc2[2 * g + 0], vv, t.x);
            fma2(acc2[2 * g + 1], vv, t.y);
        }
    }
    float* ob = out + (size_t)b * 64 * HW + p;
#pragma unroll
    for (int j = 0; j < 32; j++) {
        float2 f = unpack2(acc2[j]);
        ob[(size_t)(2 * j + 0) * HW] = f.x + __ldg(bias + 2 * j + 0);
        ob[(size_t)(2 * j + 1) * HW] = f.y + __ldg(bias + 2 * j + 1);
    }
}

// ---------------------------------------------------------------------------
// bilinear 2x upsample, jax.image.resize semantics
// ---------------------------------------------------------------------------
__global__ void __launch_bounds__(256) upsample2x_kernel(
    const float* __restrict__ in, float* __restrict__ out, int BC, int H, int W)
{
    const int W2 = 2 * W, H2 = 2 * H;
    int idx = blockIdx.x * 256 + threadIdx.x;
    int total = BC * H2 * W2;
    if (idx >= total) return;
    int x = idx % W2;
    int t = idx / W2;
    int y = t % H2;
    int c = t / H2;
    float sy = y * 0.5f - 0.25f;
    float sx = x * 0.5f - 0.25f;
    float y0f = floorf(sy), x0f = floorf(sx);
    float wy = sy - y0f, wx = sx - x0f;
    int y0 = (int)y0f, x0 = (int)x0f;
    int yc0 = min(max(y0, 0), H - 1), yc1 = min(max(y0 + 1, 0), H - 1);
    int xc0 = min(max(x0, 0), W - 1), xc1 = min(max(x0 + 1, 0), W - 1);
    const float* p = in + (size_t)c * H * W;
    float v = (1.0f - wy) * ((1.0f - wx) * __ldg(p + yc0 * W + xc0) + wx * __ldg(p + yc0 * W + xc1))
            +         wy  * ((1.0f - wx) * __ldg(p + yc1 * W + xc0) + wx * __ldg(p + yc1 * W + xc1));
    out[idx] = v;
}

// ---------------------------------------------------------------------------
// DCNv2 + ELU (+ optional fused residual-upsample add for stage 2)
// R12 core with CONSECUTIVE-PIXEL mapping: thread owns px = 4*lane + q
// (q=0..3) -> phase-1 STS.128 and phase-2 LDS.128 on s_s (was 4x STS.32 /
// 4x LDS.32). Same bytes, ~2100 fewer issue slots per thread.
// Phase 1: warp w gathers channels [16w,16w+16) for its 4 px/thread -> s_s.
// Phase 2: warp w owns outputs [16w,16w+16) x 128 px; weights via LDS128.
// PREF: offset prefetch across taps (measured: on for RES variant only).
// ---------------------------------------------------------------------------
template <int H, int W, int TILEW, int ROWS, bool RES, bool PREF>
__global__ void __launch_bounds__(128) dcn_kernel(
    const float* __restrict__ img,   // (B,64,H,W)
    const float* __restrict__ off,   // (B,27,H,W)
    const float* __restrict__ wt,    // (9,64,64) (k,c,o)
    const float* __restrict__ bias,  // (64)
    const float* __restrict__ res,   // (B,64,H/2,W/2) or nullptr
    float* __restrict__ out)         // (B,64,H,W)
{
    static_assert(TILEW * ROWS == 128, "tile must be 128 px");
    static_assert(TILEW % 4 == 0, "4-px groups must not straddle rows");
    __shared__ __align__(16) float s_s[64][128];  // [c][px]
    __shared__ __align__(16) float w_s[4096];     // one tap's 64x64 slab

    const int tid  = threadIdx.x;
    const int lane = tid & 31;
    const int warp = tid >> 5;          // 0..3
    const int cgrp = warp * 16;         // phase-1 channel group == phase-2 o group
    const int h0 = blockIdx.y * ROWS;
    const int bx = blockIdx.x * TILEW;
    const int b  = blockIdx.z;
    const int HW = H * W;
    const float* imgb = img + (size_t)b * 64 * HW;
    const float* offb = off + (size_t)b * 27 * HW;

    // this thread's 4 pixels: px = 4*lane + q  (consecutive!)
    int pwv[4], hv[4], pidx[4];
#pragma unroll
    for (int q = 0; q < 4; q++) {
        int px  = 4 * lane + q;
        int row = px / TILEW;
        int col = px - row * TILEW;
        pwv[q] = bx + col;
        hv[q]  = h0 + row;
        pidx[q] = hv[q] * W + pwv[q];
    }

    unsigned long long acc[32];   // [o-pair j(8)][px q(4)] -> acc[j*4+q]
#pragma unroll
    for (int i = 0; i < 32; i++) acc[i] = 0ULL;

    float pdy[4], pdx[4], pmz[4];
    if (PREF) {
#pragma unroll
        for (int q = 0; q < 4; q++) {
            pdy[q] = __ldg(offb + 0 * HW + pidx[q]);
            pdx[q] = __ldg(offb + 1 * HW + pidx[q]);
            pmz[q] = __ldg(offb + 18 * HW + pidx[q]);
        }
    }

    for (int k = 0; k < 9; k++) {
        __syncthreads();  // protect s_s / w_s against previous iteration's readers
        // stage this tap's 64x64 weight slab (128 threads x 8 float4)
        {
            const float4* src = (const float4*)(wt + k * 4096);
            float4* dst = (float4*)w_s;
#pragma unroll
            for (int i = tid; i < 1024; i += 128) dst[i] = src[i];
        }

        // tap params for 4 pixels
        float w00[4], w01[4], w10[4], w11[4];
        int i00[4], i01[4], i10[4], i11[4];
#pragma unroll
        for (int q = 0; q < 4; q++) {
            float dy, dx, mz;
            if (PREF) {
                dy = pdy[q]; dx = pdx[q]; mz = pmz[q];
            } else {
                dy = __ldg(offb + (2 * k) * HW + pidx[q]);
                dx = __ldg(offb + (2 * k + 1) * HW + pidx[q]);
                mz = __ldg(offb + (18 + k) * HW + pidx[q]);
            }
            float m  = 1.0f / (1.0f + expf(-mz));

            float yy = (float)(hv[q] - 1 + k / 3) + dy;
            float xx = (float)(pwv[q] - 1 + k % 3) + dx;
            float y0f = floorf(yy), x0f = floorf(xx);
            float wy = yy - y0f, wx = xx - x0f;
            int y0 = (int)y0f, x0 = (int)x0f;
            int y1 = y0 + 1,   x1 = x0 + 1;
            float fy0 = (y0 >= 0 && y0 < H) ? 1.0f : 0.0f;
            float fy1 = (y1 >= 0 && y1 < H) ? 1.0f : 0.0f;
            float fx0 = (x0 >= 0 && x0 < W) ? 1.0f : 0.0f;
            float fx1 = (x1 >= 0 && x1 < W) ? 1.0f : 0.0f;
            w00[q] = (1.0f - wy) * (1.0f - wx) * fy0 * fx0 * m;
            w01[q] = (1.0f - wy) * wx          * fy0 * fx1 * m;
            w10[q] = wy          * (1.0f - wx) * fy1 * fx0 * m;
            w11[q] = wy          * wx          * fy1 * fx1 * m;
            int yc0 = min(max(y0, 0), H - 1), yc1 = min(max(y1, 0), H - 1);
            int xc0 = min(max(x0, 0), W - 1), xc1 = min(max(x1, 0), W - 1);
            i00[q] = yc0 * W + xc0; i01[q] = yc0 * W + xc1;
            i10[q] = yc1 * W + xc0; i11[q] = yc1 * W + xc1;
        }

        // phase 1: this warp's 16 channels x this thread's 4 consecutive px.
        // One STS.128 per channel.
        const float* pc = imgb + (size_t)cgrp * HW;
#pragma unroll
        for (int cc = 0; cc < 16; cc++) {
            float4 sv;
            sv.x = w00[0] * __ldg(pc + i00[0]) + w01[0] * __ldg(pc + i01[0])
                 + w10[0] * __ldg(pc + i10[0]) + w11[0] * __ldg(pc + i11[0]);
            sv.y = w00[1] * __ldg(pc + i00[1]) + w01[1] * __ldg(pc + i01[1])
                 + w10[1] * __ldg(pc + i10[1]) + w11[1] * __ldg(pc + i11[1]);
            sv.z = w00[2] * __ldg(pc + i00[2]) + w01[2] * __ldg(pc + i01[2])
                 + w10[2] * __ldg(pc + i10[2]) + w11[2] * __ldg(pc + i11[2]);
            sv.w = w00[3] * __ldg(pc + i00[3]) + w01[3] * __ldg(pc + i01[3])
                 + w10[3] * __ldg(pc + i10[3]) + w11[3] * __ldg(pc + i11[3]);
            *(float4*)&s_s[cgrp + cc][4 * lane] = sv;
            pc += HW;
        }
        __syncthreads();

        // prefetch NEXT tap's offsets (latency hides under GEMM below)
        if (PREF && k < 8) {
#pragma unroll
            for (int q = 0; q < 4; q++) {
                pdy[q] = __ldg(offb + (2 * k + 2) * HW + pidx[q]);
                pdx[q] = __ldg(offb + (2 * k + 3) * HW + pidx[q]);
                pmz[q] = __ldg(offb + (19 + k) * HW + pidx[q]);
            }
        }

        // phase 2: warp's 16 outputs x 128 pixels; ONE LDS.128 per c for the
        // thread's 4 consecutive pixels, 32 FFMA2 per c per thread.
#pragma unroll 4
        for (int c = 0; c < 64; c++) {
            float4 sv = *(const float4*)&s_s[c][4 * lane];
            unsigned long long v[4];
            v[0] = pack2(sv.x); v[1] = pack2(sv.y);
            v[2] = pack2(sv.z); v[3] = pack2(sv.w);
            const ulonglong2* wr = (const ulonglong2*)(w_s + c * 64 + cgrp);
            ulonglong2 wp0 = wr[0], wp1 = wr[1], wp2 = wr[2], wp3 = wr[3];
#pragma unroll
            for (int q = 0; q < 4; q++) {
                fma2(acc[0 * 4 + q], v[q], wp0.x);
                fma2(acc[1 * 4 + q], v[q], wp0.y);
                fma2(acc[2 * 4 + q], v[q], wp1.x);
                fma2(acc[3 * 4 + q], v[q], wp1.y);
                fma2(acc[4 * 4 + q], v[q], wp2.x);
                fma2(acc[5 * 4 + q], v[q], wp2.y);
                fma2(acc[6 * 4 + q], v[q], wp3.x);
                fma2(acc[7 * 4 + q], v[q], wp3.y);
            }
        }
    }

    // epilogue: bias, ELU, optional fused residual 2x upsample (per pixel)
    const int Hh = H / 2, Wh = W / 2;
    float rw00[4], rw01[4], rw10[4], rw11[4];
    int ri00[4], ri01[4], ri10[4], ri11[4];
    if (RES) {
#pragma unroll
        for (int q = 0; q < 4; q++) {
            float sy = hv[q]  * 0.5f - 0.25f;
            float sx = pwv[q] * 0.5f - 0.25f;
            float y0f = floorf(sy), x0f = floorf(sx);
            float wy = sy - y0f, wx = sx - x0f;
            int y0 = (int)y0f, x0 = (int)x0f;
            int yc0 = min(max(y0, 0), Hh - 1), yc1 = min(max(y0 + 1, 0), Hh - 1);
            int xc0 = min(max(x0, 0), Wh - 1), xc1 = min(max(x0 + 1, 0), Wh - 1);
            rw00[q] = (1.0f - wy) * (1.0f - wx);
            rw01[q] = (1.0f - wy) * wx;
            rw10[q] = wy * (1.0f - wx);
            rw11[q] = wy * wx;
            ri00[q] = yc0 * Wh + xc0; ri01[q] = yc0 * Wh + xc1;
            ri10[q] = yc1 * Wh + xc0; ri11[q] = yc1 * Wh + xc1;
        }
    }
    const float* resb = RES ? (res + (size_t)b * 64 * Hh * Wh) : nullptr;

#pragma unroll
    for (int j = 0; j < 8; j++) {
        int o0 = cgrp + 2 * j;
        float b0 = __ldg(bias + o0);
        float b1 = __ldg(bias + o0 + 1);
#pragma unroll
        for (int q = 0; q < 4; q++) {
            float2 f = unpack2(acc[j * 4 + q]);
            float v0 = f.x + b0;
            float v1 = f.y + b1;
            v0 = v0 > 0.0f ? v0 : expm1f(v0);
            v1 = v1 > 0.0f ? v1 : expm1f(v1);
            if (RES) {
                const float* rp0 = resb + (size_t)o0 * Hh * Wh;
                const float* rp1 = rp0 + Hh * Wh;
                float ru = rw00[q] * __ldg(rp0 + ri00[q]) + rw01[q] * __ldg(rp0 + ri01[q])
                         + rw10[q] * __ldg(rp0 + ri10[q]) + rw11[q] * __ldg(rp0 + ri11[q]);
                float rv = rw00[q] * __ldg(rp1 + ri00[q]) + rw01[q] * __ldg(rp1 + ri01[q])
                         + rw10[q] * __ldg(rp1 + ri10[q]) + rw11[q] * __ldg(rp1 + ri11[q]);
                v0 += ru;
                v1 += rv;
            }
            out[(((size_t)b * 64 + o0)     * H + hv[q]) * W + pwv[q]] = v0;
            out[(((size_t)b * 64 + o0 + 1) * H + hv[q]) * W + pwv[q]] = v1;
        }
    }
}

// ---------------------------------------------------------------------------
// kernel_launch
// inputs: x, ow1, ob1, w1, b1, ow2, ob2, w2, b2, rw, rb
// ---------------------------------------------------------------------------
extern "C" void kernel_launch(void* const* d_in, const int* in_sizes, int n_in,
                              void* d_out, int out_size) {
    (void)in_sizes; (void)n_in; (void)out_size;
    const float* x   = (const float*)d_in[0];
    const float* ow1 = (const float*)d_in[1];
    const float* ob1 = (const float*)d_in[2];
    const float* w1  = (const float*)d_in[3];
    const float* b1  = (const float*)d_in[4];
    const float* ow2 = (const float*)d_in[5];
    const float* ob2 = (const float*)d_in[6];
    const float* w2  = (const float*)d_in[7];
    const float* b2  = (const float*)d_in[8];
    const float* rw  = (const float*)d_in[9];
    const float* rb  = (const float*)d_in[10];
    float* out = (float*)d_out;

    float *off1, *h1, *h1up, *off2, *r, *w1t, *w2t, *ow1t, *ow2t;
    cudaGetSymbolAddress((void**)&off1, g_off1);
    cudaGetSymbolAddress((void**)&h1,   g_h1);
    cudaGetSymbolAddress((void**)&h1up, g_h1up);
    cudaGetSymbolAddress((void**)&off2, g_off2);
    cudaGetSymbolAddress((void**)&r,    g_r);
    cudaGetSymbolAddress((void**)&w1t,  g_w1t);
    cudaGetSymbolAddress((void**)&w2t,  g_w2t);
    cudaGetSymbolAddress((void**)&ow1t, g_ow1t);
    cudaGetSymbolAddress((void**)&ow2t, g_ow2t);

    // 0: all weight transposes in one launch
    transpose_all_kernel<<<(110592 + 255) / 256, 256>>>(w1, w2, ow1, ow2);

    // 1: residual path 1x1 conv (independent of stage 1)
    conv1x1_kernel<<<dim3((H1_ * W1_ + 255) / 256, B_), 256>>>(x, rw, rb, r, H1_ * W1_);

    // 2: stage-1 offsets — 16x16 tiles (grid 288; R12 measured win)
    conv3x3_27_kernel<16><<<dim3(W1_ / 16, H1_ / 16, B_), 256>>>(x, ow1t, ob1, off1, H1_, W1_);

    // 3: stage-1 dcn + elu (64x2 tile = 128 px), NO prefetch (measured best)
    dcn_kernel<H1_, W1_, 64, 2, false, false><<<dim3(W1_ / 64, H1_ / 2, B_), 128>>>(x, off1, w1t, b1, nullptr, h1);

    // 4: upsample
    upsample2x_kernel<<<(B_ * C_ * H2_ * W2_ + 255) / 256, 256>>>(h1, h1up, B_ * C_, H1_, W1_);

    // 5: stage-2 offsets — 16x32 tiles (grid 576; R12 measured best)
    conv3x3_27_kernel<32><<<dim3(W2_ / 16, H2_ / 32, B_), 256>>>(h1up, ow2t, ob2, off2, H2_, W2_);

    // 6: stage-2 dcn + elu + fused residual upsample, WITH prefetch (measured best)
    dcn_kernel<H2_, W2_, 128, 1, true, true><<<dim3(W2_ / 128, H2_, B_), 128>>>(h1up, off2, w2t, b2, r, out);
}

// round 16
// speedup vs baseline: 1.1422x; 1.1175x over previous
#include <cuda_runtime.h>
#include <math.h>

// ---------------------------------------------------------------------------
// Problem constants
//   x:  (2, 64, 192, 192)
//   out:(2, 64, 384, 384) fp32
// ---------------------------------------------------------------------------
#define B_   2
#define C_   64
#define H1_  192
#define W1_  192
#define H2_  384
#define W2_  384

// ---------------------------------------------------------------------------
// f32x2 packed-FMA helpers (sm_103a FFMA2 — only reachable via PTX)
// ---------------------------------------------------------------------------
__device__ __forceinline__ unsigned long long pack2(float v) {
    unsigned long long r;
    asm("mov.b64 %0, {%1, %1};" : "=l"(r) : "f"(v));
    return r;
}
__device__ __forceinline__ void fma2(unsigned long long& d,
                                     unsigned long long a,
                                     unsigned long long b) {
    asm("fma.rn.f32x2 %0, %1, %2, %0;" : "+l"(d) : "l"(a), "l"(b));
}
__device__ __forceinline__ float2 unpack2(unsigned long long v) {
    float2 f;
    asm("mov.b64 {%0, %1}, %2;" : "=f"(f.x), "=f"(f.y) : "l"(v));
    return f;
}

// fast sigmoid / ELU via MUFU.EX2 (error ~1e-7, threshold is 1e-3)
__device__ __forceinline__ float fast_sigmoid(float z) {
    return 1.0f / (1.0f + __expf(-z));
}
__device__ __forceinline__ float fast_elu(float v) {
    return v > 0.0f ? v : (__expf(v) - 1.0f);
}

// ---------------------------------------------------------------------------
// Scratch (static device globals; no cudaMalloc allowed)
// ---------------------------------------------------------------------------
__device__ float g_off1[B_ * 27 * H1_ * W1_];   // offsets stage 1
__device__ float g_h1  [B_ * C_ * H1_ * W1_];   // elu(dcn1)
__device__ float g_h1up[B_ * C_ * H2_ * W2_];   // upsample2x(h1)
__device__ float g_off2[B_ * 27 * H2_ * W2_];   // offsets stage 2
__device__ float g_r   [B_ * C_ * H1_ * W1_];   // 1x1 residual conv
__device__ float g_w1t [9 * 64 * 64];           // dcn1 weights (k,c,o)
__device__ float g_w2t [9 * 64 * 64];           // dcn2 weights (k,c,o)
__device__ float g_ow1t[64 * 9 * 32];           // offset conv1 weights (c,k,o-pad32)
__device__ float g_ow2t[64 * 9 * 32];           // offset conv2 weights (c,k,o-pad32)

// ---------------------------------------------------------------------------
// Merged weight transposes (one launch)
// ---------------------------------------------------------------------------
__global__ void transpose_all_kernel(const float* __restrict__ w1,
                                     const float* __restrict__ w2,
                                     const float* __restrict__ ow1,
                                     const float* __restrict__ ow2) {
    int i = blockIdx.x * 256 + threadIdx.x;
    if (i < 2 * 36864) {
        const float* w = (i < 36864) ? w1 : w2;
        float* wt = (i < 36864) ? g_w1t : g_w2t;
        int j = (i < 36864) ? i : i - 36864;
        int o = j & 63;
        int c = (j >> 6) & 63;
        int k = j >> 12;
        wt[j] = w[(o * 64 + c) * 9 + k];
    } else {
        int j = i - 2 * 36864;
        if (j >= 2 * 18432) return;
        const float* w = (j < 18432) ? ow1 : ow2;
        float* wt = (j < 18432) ? g_ow1t : g_ow2t;
        int jj = (j < 18432) ? j : j - 18432;
        int c = jj / 288;
        int r = jj - c * 288;
        int k = r >> 5;
        int o = r & 31;
        wt[jj] = (o < 27) ? w[(o * 64 + c) * 9 + k] : 0.0f;
    }
}

// ---------------------------------------------------------------------------
// 3x3 conv, Cin=64, Cout=27 (28 acc = 14 f32x2 per row group), pad=1, NCHW
// Templated tile height TR: block = 256 thr = 16 x TR tile, TR/16 rows/thread.
// Double-buffered halo+weights, one sync per channel.  (R12 configuration)
// ---------------------------------------------------------------------------
template <int TR>
__global__ void __launch_bounds__(256) conv3x3_27_kernel(
    const float* __restrict__ in,    // (B,64,H,W)
    const float* __restrict__ wt,    // (64,9,32) transposed+padded
    const float* __restrict__ bias,  // (27)
    float* __restrict__ out,         // (B,27,H,W)
    int H, int W)
{
    constexpr int NR = TR + 2;
    constexpr int CNT = NR * 18;
    constexpr int SLOTS = (CNT + 255) / 256;
    constexpr int RG = TR / 16;

    __shared__ __align__(16) float tile[2][NR][18];
    __shared__ __align__(16) float wsm[2][288];

    const int tid = threadIdx.x;
    const int tx = tid & 15;
    const int ty = tid >> 4;
    const int bx = blockIdx.x * 16;
    const int by = blockIdx.y * TR;
    const int b  = blockIdx.z;

    int gofs[SLOTS];
    bool gval[SLOTS];
    bool ghave[SLOTS];
#pragma unroll
    for (int s = 0; s < SLOTS; s++) {
        int idx = tid + s * 256;
        ghave[s] = (idx < CNT);
        int iy = idx / 18, ix = idx - iy * 18;
        int yy = by + iy - 1, xx = bx + ix - 1;
        gval[s] = ghave[s] && (yy >= 0 && yy < H && xx >= 0 && xx < W);
        gofs[s] = yy * W + xx;
    }
    const bool haveW1 = (tid < 32);

    unsigned long long acc2[RG][14];
#pragma unroll
    for (int rg = 0; rg < RG; rg++)
#pragma unroll
        for (int j = 0; j < 14; j++) acc2[rg][j] = 0ULL;

    const float* pc = in + (size_t)b * 64 * H * W;
    const float* pw = wt;
    const int HW = H * W;

#pragma unroll
    for (int s = 0; s < SLOTS; s++)
        if (ghave[s])
            ((float*)tile[0])[tid + s * 256] = gval[s] ? __ldg(pc + gofs[s]) : 0.0f;
    wsm[0][tid] = __ldg(pw + tid);
    if (haveW1) wsm[0][tid + 256] = __ldg(pw + tid + 256);
    __syncthreads();

    for (int c = 0; c < 64; c++) {
        const int cur = c & 1;

        float nv[SLOTS];
        float nw0 = 0.0f, nw1 = 0.0f;
        if (c < 63) {
            const float* pn = pc + HW;
            const float* pwn = pw + 288;
#pragma unroll
            for (int s = 0; s < SLOTS; s++)
                nv[s] = (ghave[s] && gval[s]) ? __ldg(pn + gofs[s]) : 0.0f;
            nw0 = __ldg(pwn + tid);
            if (haveW1) nw1 = __ldg(pwn + tid + 256);
        }

#pragma unroll
        for (int k = 0; k < 9; k++) {
            const ulonglong2* wr = (const ulonglong2*)(&wsm[cur][k * 32]);
#pragma unroll
            for (int rg = 0; rg < RG; rg++) {
                float xv = tile[cur][ty + rg * 16 + k / 3][tx + k % 3];
                unsigned long long xv2 = pack2(xv);
#pragma unroll
                for (int g = 0; g < 7; g++) {
                    ulonglong2 wv = wr[g];
                    fma2(acc2[rg][2 * g + 0], xv2, wv.x);
                    fma2(acc2[rg][2 * g + 1], xv2, wv.y);
                }
            }
        }

        if (c < 63) {
            const int nxt = cur ^ 1;
#pragma unroll
            for (int s = 0; s < SLOTS; s++)
                if (ghave[s]) ((float*)tile[nxt])[tid + s * 256] = nv[s];
            wsm[nxt][tid] = nw0;
            if (haveW1) wsm[nxt][tid + 256] = nw1;
        }
        __syncthreads();
        pc += HW;
        pw += 288;
    }

    const int gx = bx + tx;
#pragma unroll
    for (int rg = 0; rg < RG; rg++) {
        const int gy = by + ty + rg * 16;
        float fa[28];
#pragma unroll
        for (int j = 0; j < 14; j++) {
            float2 t0 = unpack2(acc2[rg][j]);
            fa[2 * j] = t0.x; fa[2 * j + 1] = t0.y;
        }
#pragma unroll
        for (int o = 0; o < 27; o++)
            out[(((size_t)b * 27 + o) * H + gy) * W + gx] = fa[o] + __ldg(bias + o);
    }
}

// ---------------------------------------------------------------------------
// 1x1 conv, 64->64 (residual path), f32x2
// ---------------------------------------------------------------------------
__global__ void __launch_bounds__(256) conv1x1_kernel(
    const float* __restrict__ in,   // (B,64,HW)
    const float* __restrict__ w,    // (64,64) (o,c)
    const float* __restrict__ bias, // (64)
    float* __restrict__ out,        // (B,64,HW)
    int HW)
{
    __shared__ __align__(16) float ws[64 * 64];  // transposed: ws[c*64+o]
    const int tid = threadIdx.x;
    for (int i = tid; i < 4096; i += 256) {
        int c = i >> 6, o = i & 63;
        ws[i] = __ldg(w + o * 64 + c);
    }
    __syncthreads();

    const int b = blockIdx.y;
    const int p = blockIdx.x * 256 + tid;
    if (p >= HW) return;

    const float* inb = in + (size_t)b * 64 * HW + p;
    unsigned long long acc2[32];
#pragma unroll
    for (int j = 0; j < 32; j++) acc2[j] = 0ULL;

    for (int c = 0; c < 64; c++) {
        float xv = __ldg(inb + (size_t)c * HW);
        unsigned long long vv = pack2(xv);
        const ulonglong2* wr = (const ulonglong2*)(ws + c * 64);
#pragma unroll
        for (int g = 0; g < 16; g++) {
            ulonglong2 t = wr[g];
            fma2(acc2[2 * g + 0], vv, t.x);
            fma2(acc2[2 * g + 1], vv, t.y);
        }
    }
    float* ob = out + (size_t)b * 64 * HW + p;
#pragma unroll
    for (int j = 0; j < 32; j++) {
        float2 f = unpack2(acc2[j]);
        ob[(size_t)(2 * j + 0) * HW] = f.x + __ldg(bias + 2 * j + 0);
        ob[(size_t)(2 * j + 1) * HW] = f.y + __ldg(bias + 2 * j + 1);
    }
}

// ---------------------------------------------------------------------------
// bilinear 2x upsample, jax.image.resize semantics
// ---------------------------------------------------------------------------
__global__ void __launch_bounds__(256) upsample2x_kernel(
    const float* __restrict__ in, float* __restrict__ out, int BC, int H, int W)
{
    const int W2 = 2 * W, H2 = 2 * H;
    int idx = blockIdx.x * 256 + threadIdx.x;
    int total = BC * H2 * W2;
    if (idx >= total) return;
    int x = idx % W2;
    int t = idx / W2;
    int y = t % H2;
    int c = t / H2;
    float sy = y * 0.5f - 0.25f;
    float sx = x * 0.5f - 0.25f;
    float y0f = floorf(sy), x0f = floorf(sx);
    float wy = sy - y0f, wx = sx - x0f;
    int y0 = (int)y0f, x0 = (int)x0f;
    int yc0 = min(max(y0, 0), H - 1), yc1 = min(max(y0 + 1, 0), H - 1);
    int xc0 = min(max(x0, 0), W - 1), xc1 = min(max(x0 + 1, 0), W - 1);
    const float* p = in + (size_t)c * H * W;
    float v = (1.0f - wy) * ((1.0f - wx) * __ldg(p + yc0 * W + xc0) + wx * __ldg(p + yc0 * W + xc1))
            +         wy  * ((1.0f - wx) * __ldg(p + yc1 * W + xc0) + wx * __ldg(p + yc1 * W + xc1));
    out[idx] = v;
}

// ---------------------------------------------------------------------------
// DCNv2 + ELU (+ optional fused residual-upsample add for stage 2)
// EXACT R12 core (best measured: 1182.5us total; dcn1 165us, 128 regs,
// occ 20%), with fast MUFU-based sigmoid/ELU as the only change.
// Block = 128 threads = 4 warps. Tile = 128 pixels (TILEW cols x ROWS rows).
// Phase 1: warp w gathers channels [16w,16w+16) for its 4 px/thread -> s_s.
// Phase 2: warp w owns outputs [16w,16w+16) x 128 px; weights via LDS128.
// PREF: offset prefetch across taps (measured: on for RES variant only).
// ---------------------------------------------------------------------------
template <int H, int W, int TILEW, int ROWS, bool RES, bool PREF>
__global__ void __launch_bounds__(128) dcn_kernel(
    const float* __restrict__ img,   // (B,64,H,W)
    const float* __restrict__ off,   // (B,27,H,W)
    const float* __restrict__ wt,    // (9,64,64) (k,c,o)
    const float* __restrict__ bias,  // (64)
    const float* __restrict__ res,   // (B,64,H/2,W/2) or nullptr
    float* __restrict__ out)         // (B,64,H,W)
{
    static_assert(TILEW * ROWS == 128, "tile must be 128 px");
    __shared__ __align__(16) float s_s[64][128];  // [c][px]
    __shared__ __align__(16) float w_s[4096];     // one tap's 64x64 slab

    const int tid  = threadIdx.x;
    const int lane = tid & 31;
    const int warp = tid >> 5;          // 0..3
    const int cgrp = warp * 16;         // phase-1 channel group == phase-2 o group
    const int h0 = blockIdx.y * ROWS;
    const int bx = blockIdx.x * TILEW;
    const int b  = blockIdx.z;
    const int HW = H * W;
    const float* imgb = img + (size_t)b * 64 * HW;
    const float* offb = off + (size_t)b * 27 * HW;

    // this thread's 4 pixels: px = lane + q*32
    int pwv[4], hv[4], pidx[4];
#pragma unroll
    for (int q = 0; q < 4; q++) {
        int px  = lane + q * 32;
        int row = px / TILEW;
        int col = px - row * TILEW;
        pwv[q] = bx + col;
        hv[q]  = h0 + row;
        pidx[q] = hv[q] * W + pwv[q];
    }

    unsigned long long acc[32];   // [o-pair j(8)][px q(4)] -> acc[j*4+q]
#pragma unroll
    for (int i = 0; i < 32; i++) acc[i] = 0ULL;

    float pdy[4], pdx[4], pmz[4];
    if (PREF) {
#pragma unroll
        for (int q = 0; q < 4; q++) {
            pdy[q] = __ldg(offb + 0 * HW + pidx[q]);
            pdx[q] = __ldg(offb + 1 * HW + pidx[q]);
            pmz[q] = __ldg(offb + 18 * HW + pidx[q]);
        }
    }

    for (int k = 0; k < 9; k++) {
        __syncthreads();  // protect s_s / w_s against previous iteration's readers
        // stage this tap's 64x64 weight slab (128 threads x 8 float4)
        {
            const float4* src = (const float4*)(wt + k * 4096);
            float4* dst = (float4*)w_s;
#pragma unroll
            for (int i = tid; i < 1024; i += 128) dst[i] = src[i];
        }

        // tap params for 4 pixels
        float w00[4], w01[4], w10[4], w11[4];
        int i00[4], i01[4], i10[4], i11[4];
#pragma unroll
        for (int q = 0; q < 4; q++) {
            float dy, dx, mz;
            if (PREF) {
                dy = pdy[q]; dx = pdx[q]; mz = pmz[q];
            } else {
                dy = __ldg(offb + (2 * k) * HW + pidx[q]);
                dx = __ldg(offb + (2 * k + 1) * HW + pidx[q]);
                mz = __ldg(offb + (18 + k) * HW + pidx[q]);
            }
            float m  = fast_sigmoid(mz);

            float yy = (float)(hv[q] - 1 + k / 3) + dy;
            float xx = (float)(pwv[q] - 1 + k % 3) + dx;
            float y0f = floorf(yy), x0f = floorf(xx);
            float wy = yy - y0f, wx = xx - x0f;
            int y0 = (int)y0f, x0 = (int)x0f;
            int y1 = y0 + 1,   x1 = x0 + 1;
            float fy0 = (y0 >= 0 && y0 < H) ? 1.0f : 0.0f;
            float fy1 = (y1 >= 0 && y1 < H) ? 1.0f : 0.0f;
            float fx0 = (x0 >= 0 && x0 < W) ? 1.0f : 0.0f;
            float fx1 = (x1 >= 0 && x1 < W) ? 1.0f : 0.0f;
            w00[q] = (1.0f - wy) * (1.0f - wx) * fy0 * fx0 * m;
            w01[q] = (1.0f - wy) * wx          * fy0 * fx1 * m;
            w10[q] = wy          * (1.0f - wx) * fy1 * fx0 * m;
            w11[q] = wy          * wx          * fy1 * fx1 * m;
            int yc0 = min(max(y0, 0), H - 1), yc1 = min(max(y1, 0), H - 1);
            int xc0 = min(max(x0, 0), W - 1), xc1 = min(max(x1, 0), W - 1);
            i00[q] = yc0 * W + xc0; i01[q] = yc0 * W + xc1;
            i10[q] = yc1 * W + xc0; i11[q] = yc1 * W + xc1;
        }

        // phase 1: this warp's 16 channels x this thread's 4 pixels
        const float* pc = imgb + (size_t)cgrp * HW;
#pragma unroll
        for (int cc = 0; cc < 16; cc++) {
#pragma unroll
            for (int q = 0; q < 4; q++) {
                float s = w00[q] * __ldg(pc + i00[q]) + w01[q] * __ldg(pc + i01[q])
                        + w10[q] * __ldg(pc + i10[q]) + w11[q] * __ldg(pc + i11[q]);
                s_s[cgrp + cc][lane + q * 32] = s;
            }
            pc += HW;
        }
        __syncthreads();

        // prefetch NEXT tap's offsets (latency hides under GEMM below)
        if (PREF && k < 8) {
#pragma unroll
            for (int q = 0; q < 4; q++) {
                pdy[q] = __ldg(offb + (2 * k + 2) * HW + pidx[q]);
                pdx[q] = __ldg(offb + (2 * k + 3) * HW + pidx[q]);
                pmz[q] = __ldg(offb + (19 + k) * HW + pidx[q]);
            }
        }

        // phase 2: warp's 16 outputs x 128 pixels, 32 FFMA2 per c per thread
#pragma unroll 4
        for (int c = 0; c < 64; c++) {
            unsigned long long v[4];
#pragma unroll
            for (int q = 0; q < 4; q++) v[q] = pack2(s_s[c][lane + q * 32]);
            const ulonglong2* wr = (const ulonglong2*)(w_s + c * 64 + cgrp);
            ulonglong2 wp0 = wr[0], wp1 = wr[1], wp2 = wr[2], wp3 = wr[3];
#pragma unroll
            for (int q = 0; q < 4; q++) {
                fma2(acc[0 * 4 + q], v[q], wp0.x);
                fma2(acc[1 * 4 + q], v[q], wp0.y);
                fma2(acc[2 * 4 + q], v[q], wp1.x);
                fma2(acc[3 * 4 + q], v[q], wp1.y);
                fma2(acc[4 * 4 + q], v[q], wp2.x);
                fma2(acc[5 * 4 + q], v[q], wp2.y);
                fma2(acc[6 * 4 + q], v[q], wp3.x);
                fma2(acc[7 * 4 + q], v[q], wp3.y);
            }
        }
    }

    // epilogue: bias, ELU, optional fused residual 2x upsample (per pixel)
    const int Hh = H / 2, Wh = W / 2;
    float rw00[4], rw01[4], rw10[4], rw11[4];
    int ri00[4], ri01[4], ri10[4], ri11[4];
    if (RES) {
#pragma unroll
        for (int q = 0; q < 4; q++) {
            float sy = hv[q]  * 0.5f - 0.25f;
            float sx = pwv[q] * 0.5f - 0.25f;
            float y0f = floorf(sy), x0f = floorf(sx);
            float wy = sy - y0f, wx = sx - x0f;
            int y0 = (int)y0f, x0 = (int)x0f;
            int yc0 = min(max(y0, 0), Hh - 1), yc1 = min(max(y0 + 1, 0), Hh - 1);
            int xc0 = min(max(x0, 0), Wh - 1), xc1 = min(max(x0 + 1, 0), Wh - 1);
            rw00[q] = (1.0f - wy) * (1.0f - wx);
            rw01[q] = (1.0f - wy) * wx;
            rw10[q] = wy * (1.0f - wx);
            rw11[q] = wy * wx;
            ri00[q] = yc0 * Wh + xc0; ri01[q] = yc0 * Wh + xc1;
            ri10[q] = yc1 * Wh + xc0; ri11[q] = yc1 * Wh + xc1;
        }
    }
    const float* resb = RES ? (res + (size_t)b * 64 * Hh * Wh) : nullptr;

#pragma unroll
    for (int j = 0; j < 8; j++) {
        int o0 = cgrp + 2 * j;
        float b0 = __ldg(bias + o0);
        float b1 = __ldg(bias + o0 + 1);
#pragma unroll
        for (int q = 0; q < 4; q++) {
            float2 f = unpack2(acc[j * 4 + q]);
            float v0 = fast_elu(f.x + b0);
            float v1 = fast_elu(f.y + b1);
            if (RES) {
                const float* rp0 = resb + (size_t)o0 * Hh * Wh;
                const float* rp1 = rp0 + Hh * Wh;
                float ru = rw00[q] * __ldg(rp0 + ri00[q]) + rw01[q] * __ldg(rp0 + ri01[q])
                         + rw10[q] * __ldg(rp0 + ri10[q]) + rw11[q] * __ldg(rp0 + ri11[q]);
                float rv = rw00[q] * __ldg(rp1 + ri00[q]) + rw01[q] * __ldg(rp1 + ri01[q])
                         + rw10[q] * __ldg(rp1 + ri10[q]) + rw11[q] * __ldg(rp1 + ri11[q]);
                v0 += ru;
                v1 += rv;
            }
            out[(((size_t)b * 64 + o0)     * H + hv[q]) * W + pwv[q]] = v0;
            out[(((size_t)b * 64 + o0 + 1) * H + hv[q]) * W + pwv[q]] = v1;
        }
    }
}

// ---------------------------------------------------------------------------
// kernel_launch
// inputs: x, ow1, ob1, w1, b1, ow2, ob2, w2, b2, rw, rb
// ---------------------------------------------------------------------------
extern "C" void kernel_launch(void* const* d_in, const int* in_sizes, int n_in,
                              void* d_out, int out_size) {
    (void)in_sizes; (void)n_in; (void)out_size;
    const float* x   = (const float*)d_in[0];
    const float* ow1 = (const float*)d_in[1];
    const float* ob1 = (const float*)d_in[2];
    const float* w1  = (const float*)d_in[3];
    const float* b1  = (const float*)d_in[4];
    const float* ow2 = (const float*)d_in[5];
    const float* ob2 = (const float*)d_in[6];
    const float* w2  = (const float*)d_in[7];
    const float* b2  = (const float*)d_in[8];
    const float* rw  = (const float*)d_in[9];
    const float* rb  = (const float*)d_in[10];
    float* out = (float*)d_out;

    float *off1, *h1, *h1up, *off2, *r, *w1t, *w2t, *ow1t, *ow2t;
    cudaGetSymbolAddress((void**)&off1, g_off1);
    cudaGetSymbolAddress((void**)&h1,   g_h1);
    cudaGetSymbolAddress((void**)&h1up, g_h1up);
    cudaGetSymbolAddress((void**)&off2, g_off2);
    cudaGetSymbolAddress((void**)&r,    g_r);
    cudaGetSymbolAddress((void**)&w1t,  g_w1t);
    cudaGetSymbolAddress((void**)&w2t,  g_w2t);
    cudaGetSymbolAddress((void**)&ow1t, g_ow1t);
    cudaGetSymbolAddress((void**)&ow2t, g_ow2t);

    // 0: all weight transposes in one launch
    transpose_all_kernel<<<(110592 + 255) / 256, 256>>>(w1, w2, ow1, ow2);

    // 1: residual path 1x1 conv (independent of stage 1)
    conv1x1_kernel<<<dim3((H1_ * W1_ + 255) / 256, B_), 256>>>(x, rw, rb, r, H1_ * W1_);

    // 2: stage-1 offsets — 16x16 tiles (grid 288; R12 measured win)
    conv3x3_27_kernel<16><<<dim3(W1_ / 16, H1_ / 16, B_), 256>>>(x, ow1t, ob1, off1, H1_, W1_);

    // 3: stage-1 dcn + elu (64x2 tile = 128 px), NO prefetch (measured best)
    dcn_kernel<H1_, W1_, 64, 2, false, false><<<dim3(W1_ / 64, H1_ / 2, B_), 128>>>(x, off1, w1t, b1, nullptr, h1);

    // 4: upsample
    upsample2x_kernel<<<(B_ * C_ * H2_ * W2_ + 255) / 256, 256>>>(h1, h1up, B_ * C_, H1_, W1_);

    // 5: stage-2 offsets — 16x32 tiles (grid 576; R12 measured best)
    conv3x3_27_kernel<32><<<dim3(W2_ / 16, H2_ / 32, B_), 256>>>(h1up, ow2t, ob2, off2, H2_, W2_);

    // 6: stage-2 dcn + elu + fused residual upsample, WITH prefetch (measured best)
    dcn_kernel<H2_, W2_, 128, 1, true, true><<<dim3(W2_ / 128, H2_, B_), 128>>>(h1up, off2, w2t, b2, r, out);
}